// round 4
// baseline (speedup 1.0000x reference)
#include <cuda_runtime.h>
#include <math.h>

#define NN 4096
#define DD 512
#define BM 128
#define BN 128
#define BK 16
#define CCH 8                       // column chunks per row-block
#define COLS_PER_CHUNK (NN / CCH)   // 512
#define TILES (COLS_PER_CHUNK / BN) // 4

#define NEGBIG (-1e30f)
#define F_GAMMA 256.0f
#define F_OP 1.25f
#define F_ON (-0.25f)
#define F_DP 0.75f
#define F_DN 0.25f

// scratch (static device globals: no runtime allocation)
__device__ float g_xn[NN * DD];          // normalized inputs, 8 MB
__device__ int   g_tg[NN];               // targets as int32
__device__ float g_part[CCH * NN * 8];   // per-(chunk,row): m_p,s_p,minp,cnt,m_n,s_n,maxn,pad
__device__ float g_row[NN];
__device__ float g_val[NN];

// ---------------- targets: dtype-detect (int32 vs int64) + convert ----------------
__global__ void ck_tgt(const void* tptr) {
    const int* p32 = (const int*)tptr;
    int lf = 1;
    for (int i = threadIdx.x; i < NN / 2; i += blockDim.x)
        if (p32[2 * i + 1] != 0) lf = 0;            // int64 LE: high words of first 2048 all zero
    int is64 = __syncthreads_and(lf);
    const long long* p64 = (const long long*)tptr;
    for (int i = threadIdx.x; i < NN; i += blockDim.x)
        g_tg[i] = is64 ? (int)p64[i] : p32[i];
}

// ---------------- row L2-normalize ----------------
__global__ void ck_norm(const float* __restrict__ x) {
    int row = blockIdx.x;
    int t = threadIdx.x;                 // 128 threads
    const float* r = x + row * DD;
    float v[4];
    float s = 0.f;
#pragma unroll
    for (int i = 0; i < 4; i++) { v[i] = r[t + 128 * i]; s += v[i] * v[i]; }
#pragma unroll
    for (int o = 16; o > 0; o >>= 1) s += __shfl_down_sync(0xffffffffu, s, o);
    __shared__ float red[4];
    if ((t & 31) == 0) red[t >> 5] = s;
    __syncthreads();
    if (t == 0) red[0] = red[0] + red[1] + red[2] + red[3];
    __syncthreads();
    float inv = 1.0f / sqrtf(red[0]);
#pragma unroll
    for (int i = 0; i < 4; i++) g_xn[row * DD + t + 128 * i] = v[i] * inv;
}

// ---------------- online-lse helpers ----------------
__device__ __forceinline__ void lse_add(float& m, float& s, float term) {
    if (term > m) { s = s * __expf(m - term) + 1.f; m = term; }
    else          { s += __expf(term - m); }
}
__device__ __forceinline__ void lse_merge(float& m, float& s, float om, float os) {
    float M = fmaxf(m, om);
    s = s * __expf(m - M) + os * __expf(om - M);
    m = M;
}

// ---------------- fused GEMM (fp32) + masked online reductions ----------------
__global__ void __launch_bounds__(256, 1) ck_main() {
    __shared__ __align__(16) float As[BK][BM + 4];
    __shared__ __align__(16) float Bs[BK][BN + 4];
    __shared__ int tcs[BN];

    const int tid = threadIdx.x;
    const int tx = tid & 15, ty = tid >> 4;
    const int chunk = blockIdx.x;
    const int rb = blockIdx.y * BM;
    const int c0b = chunk * COLS_PER_CHUNK;

    int rows[8];
#pragma unroll
    for (int i = 0; i < 4; i++) { rows[i] = ty * 4 + i; rows[i + 4] = 64 + ty * 4 + i; }
    int trow[8];
#pragma unroll
    for (int i = 0; i < 8; i++) trow[i] = g_tg[rb + rows[i]];

    // per-(thread,row) partial state across this block's columns
    float m_p[8], s_p[8], mnp[8], cnt[8], m_n[8], s_n[8], mxn[8];
#pragma unroll
    for (int i = 0; i < 8; i++) {
        m_p[i] = NEGBIG; s_p[i] = 0.f; mnp[i] = 2.f; cnt[i] = 0.f;
        m_n[i] = NEGBIG; s_n[i] = 0.f; mxn[i] = -2.f;
    }

    const int m0 = tid >> 2;          // 0..63
    const int kq = (tid & 3) * 4;     // 0,4,8,12

    for (int tile = 0; tile < TILES; tile++) {
        const int c0 = c0b + tile * BN;
        __syncthreads();              // protect tcs from previous tile's epilogue readers
        if (tid < BN) tcs[tid] = g_tg[c0 + tid];

        float acc[8][8];
#pragma unroll
        for (int i = 0; i < 8; i++)
#pragma unroll
            for (int j = 0; j < 8; j++) acc[i][j] = 0.f;

        // prefetch k-tile 0
        float4 pa0 = *(const float4*)&g_xn[(rb + m0) * DD + kq];
        float4 pa1 = *(const float4*)&g_xn[(rb + m0 + 64) * DD + kq];
        float4 pb0 = *(const float4*)&g_xn[(c0 + m0) * DD + kq];
        float4 pb1 = *(const float4*)&g_xn[(c0 + m0 + 64) * DD + kq];

        for (int kt = 0; kt < DD; kt += BK) {
            As[kq + 0][m0] = pa0.x; As[kq + 1][m0] = pa0.y; As[kq + 2][m0] = pa0.z; As[kq + 3][m0] = pa0.w;
            As[kq + 0][m0 + 64] = pa1.x; As[kq + 1][m0 + 64] = pa1.y; As[kq + 2][m0 + 64] = pa1.z; As[kq + 3][m0 + 64] = pa1.w;
            Bs[kq + 0][m0] = pb0.x; Bs[kq + 1][m0] = pb0.y; Bs[kq + 2][m0] = pb0.z; Bs[kq + 3][m0] = pb0.w;
            Bs[kq + 0][m0 + 64] = pb1.x; Bs[kq + 1][m0 + 64] = pb1.y; Bs[kq + 2][m0 + 64] = pb1.z; Bs[kq + 3][m0 + 64] = pb1.w;
            __syncthreads();

            if (kt + BK < DD) {       // prefetch next k-tile (hides LDG latency behind FFMA)
                int kn = kt + BK + kq;
                pa0 = *(const float4*)&g_xn[(rb + m0) * DD + kn];
                pa1 = *(const float4*)&g_xn[(rb + m0 + 64) * DD + kn];
                pb0 = *(const float4*)&g_xn[(c0 + m0) * DD + kn];
                pb1 = *(const float4*)&g_xn[(c0 + m0 + 64) * DD + kn];
            }
#pragma unroll
            for (int k = 0; k < BK; k++) {
                float4 a0 = *(const float4*)&As[k][ty * 4];
                float4 a1 = *(const float4*)&As[k][64 + ty * 4];
                float4 b0 = *(const float4*)&Bs[k][tx * 4];
                float4 b1 = *(const float4*)&Bs[k][64 + tx * 4];
                float a[8] = {a0.x, a0.y, a0.z, a0.w, a1.x, a1.y, a1.z, a1.w};
                float b[8] = {b0.x, b0.y, b0.z, b0.w, b1.x, b1.y, b1.z, b1.w};
#pragma unroll
                for (int i = 0; i < 8; i++)
#pragma unroll
                    for (int j = 0; j < 8; j++) acc[i][j] = fmaf(a[i], b[j], acc[i][j]);
            }
            __syncthreads();
        }

        // epilogue: masked online reductions over this 128x128 sim tile
        int cols[8], tc[8];
#pragma unroll
        for (int j = 0; j < 4; j++) { cols[j] = tx * 4 + j; cols[j + 4] = 64 + tx * 4 + j; }
#pragma unroll
        for (int j = 0; j < 8; j++) tc[j] = tcs[cols[j]];

#pragma unroll
        for (int i = 0; i < 8; i++) {
            int gr = rb + rows[i];
#pragma unroll
            for (int j = 0; j < 8; j++) {
                int gc = c0 + cols[j];
                float sv = acc[i][j];
                if (trow[i] == tc[j]) {
                    if (gr != gc) {                    // positive (exclude diagonal)
                        cnt[i] += 1.f;
                        mnp[i] = fminf(mnp[i], sv);
                        float term = -F_GAMMA * fmaxf(0.f, F_OP - sv) * (sv - F_DP);
                        lse_add(m_p[i], s_p[i], term);
                    }
                } else {                               // negative
                    mxn[i] = fmaxf(mxn[i], sv);
                    float term = F_GAMMA * fmaxf(0.f, sv - F_ON) * (sv - F_DN);
                    lse_add(m_n[i], s_n[i], term);
                }
            }
        }
    }

    // merge across the 16 tx lanes sharing the same rows (lanes [0..15] / [16..31])
#pragma unroll
    for (int i = 0; i < 8; i++) {
#pragma unroll
        for (int o = 8; o > 0; o >>= 1) {
            float om = __shfl_down_sync(0xffffffffu, m_p[i], o, 16);
            float os = __shfl_down_sync(0xffffffffu, s_p[i], o, 16);
            lse_merge(m_p[i], s_p[i], om, os);
            om = __shfl_down_sync(0xffffffffu, m_n[i], o, 16);
            os = __shfl_down_sync(0xffffffffu, s_n[i], o, 16);
            lse_merge(m_n[i], s_n[i], om, os);
            mnp[i] = fminf(mnp[i], __shfl_down_sync(0xffffffffu, mnp[i], o, 16));
            mxn[i] = fmaxf(mxn[i], __shfl_down_sync(0xffffffffu, mxn[i], o, 16));
            cnt[i] += __shfl_down_sync(0xffffffffu, cnt[i], o, 16);
        }
    }
    if (tx == 0) {
#pragma unroll
        for (int i = 0; i < 8; i++) {
            int gr = rb + rows[i];
            float* p = &g_part[(size_t)(chunk * NN + gr) * 8];
            p[0] = m_p[i]; p[1] = s_p[i]; p[2] = mnp[i]; p[3] = cnt[i];
            p[4] = m_n[i]; p[5] = s_n[i]; p[6] = mxn[i];
        }
    }
}

// ---------------- per-row finalize: merge chunks, hard-mining correction, softplus ----------------
__global__ void ck_final() {
    int r = blockIdx.x * blockDim.x + threadIdx.x;
    if (r >= NN) return;
    float m_p = NEGBIG, s_p = 0.f, mnp = 2.f, cnt = 0.f;
    float m_n = NEGBIG, s_n = 0.f, mxn = -2.f;
#pragma unroll
    for (int c = 0; c < CCH; c++) {
        const float* p = &g_part[(size_t)(c * NN + r) * 8];
        float M = fmaxf(m_p, p[0]);
        s_p = s_p * expf(m_p - M) + p[1] * expf(p[0] - M);
        m_p = M;
        mnp = fminf(mnp, p[2]);
        cnt += p[3];
        M = fmaxf(m_n, p[4]);
        s_n = s_n * expf(m_n - M) + p[5] * expf(p[4] - M);
        m_n = M;
        mxn = fmaxf(mxn, p[6]);
    }
    float npos = cnt;
    float nneg = (float)(NN - 1) - npos;
    float loss = 0.f, val = 0.f;
    if (npos > 0.5f && nneg > 0.5f) {
        float lse_p, lse_n;
        {   // hardest positive: min sim; its alpha (hence term) doubles when npos > 1
            float th = -F_GAMMA * fmaxf(0.f, F_OP - mnp) * (mnp - F_DP);
            if (npos > 1.5f) {
                float M = fmaxf(m_p, 2.f * th);
                float S = s_p * expf(m_p - M) - expf(th - M) + expf(2.f * th - M);
                lse_p = M + logf(fmaxf(S, 1e-37f));
            } else lse_p = m_p + logf(s_p);
        }
        {   // hardest negative: max sim
            float tn = F_GAMMA * fmaxf(0.f, mxn - F_ON) * (mxn - F_DN);
            if (nneg > 1.5f) {
                float M = fmaxf(m_n, 2.f * tn);
                float S = s_n * expf(m_n - M) - expf(tn - M) + expf(2.f * tn - M);
                lse_n = M + logf(fmaxf(S, 1e-37f));
            } else lse_n = m_n + logf(s_n);
        }
        float z = lse_p + lse_n;
        loss = fmaxf(z, 0.f) + log1pf(expf(-fabsf(z)));   // stable softplus
        val = 1.f;
    }
    g_row[r] = loss;
    g_val[r] = val;
}

// ---------------- deterministic scalar reduction ----------------
__global__ void ck_reduce(float* __restrict__ out) {
    int t = threadIdx.x;  // 512
    float s = 0.f, v = 0.f;
    for (int i = t; i < NN; i += 512) { s += g_row[i]; v += g_val[i]; }
#pragma unroll
    for (int o = 16; o > 0; o >>= 1) {
        s += __shfl_down_sync(0xffffffffu, s, o);
        v += __shfl_down_sync(0xffffffffu, v, o);
    }
    __shared__ float ss[16], vv[16];
    if ((t & 31) == 0) { ss[t >> 5] = s; vv[t >> 5] = v; }
    __syncthreads();
    if (t < 32) {
        s = (t < 16) ? ss[t] : 0.f;
        v = (t < 16) ? vv[t] : 0.f;
#pragma unroll
        for (int o = 8; o > 0; o >>= 1) {
            s += __shfl_down_sync(0xffffffffu, s, o);
            v += __shfl_down_sync(0xffffffffu, v, o);
        }
        if (t == 0) out[0] = s / fmaxf(v, 1.f);
    }
}

extern "C" void kernel_launch(void* const* d_in, const int* in_sizes, int n_in,
                              void* d_out, int out_size) {
    const float* x = (const float*)d_in[0];
    const void* tg = d_in[1];
    float* out = (float*)d_out;
    (void)in_sizes; (void)n_in; (void)out_size;

    ck_tgt<<<1, 256>>>(tg);
    ck_norm<<<NN, 128>>>(x);
    dim3 grid(CCH, NN / BM);
    ck_main<<<grid, 256>>>();
    ck_final<<<NN / 128, 128>>>();
    ck_reduce<<<1, 512>>>(out);
}

// round 9
// speedup vs baseline: 2.0814x; 2.0814x over previous
#include <cuda_runtime.h>
#include <cuda_bf16.h>
#include <stdint.h>
#include <math.h>

#define NN 4096
#define DD 512
#define BM 128
#define CCH 8
#define COLS_PER_CHUNK 512
#define TILES 4
#define KC 64                       // K elems per pipeline chunk
#define NCH (DD / KC)               // 8 chunks per tile
#define GCH (TILES * NCH)           // 32 total chunk-stages

#define NEGBIG (-1e30f)
#define F_GAMMA 256.0f
#define F_OP 1.25f
#define F_ON (-0.25f)
#define F_DP 0.75f
#define F_DN 0.25f

// smem: [tcs 2KB][stage0 64KB][stage1 64KB]; stage = Ahi(16K) Alo(16K) Bhi(16K) Blo(16K)
#define OFF_TCS 0
#define OFF_STAGE 2048
#define STAGE_BYTES 65536
#define SMEM_TOTAL (OFF_STAGE + 2 * STAGE_BYTES)   // 133120

// ---------------- scratch ----------------
__device__ __nv_bfloat16 g_hi[NN * DD];
__device__ __nv_bfloat16 g_lo[NN * DD];
__device__ int   g_tg[NN];
__device__ float g_part[CCH * NN * 8];
__device__ float g_row[NN];
__device__ float g_val[NN];

// ---------------- PTX helpers (all sm_80-level; no 'a' features) ----------------
__device__ __forceinline__ uint32_t smem_u32(const void* p) {
    uint32_t a;
    asm("{ .reg .u64 t; cvta.to.shared.u64 t, %1; cvt.u32.u64 %0, t; }" : "=r"(a) : "l"(p));
    return a;
}
__device__ __forceinline__ void cp16(uint32_t dst, const void* src) {
    asm volatile("cp.async.cg.shared.global [%0], [%1], 16;" :: "r"(dst), "l"(src) : "memory");
}
__device__ __forceinline__ void cp_commit() { asm volatile("cp.async.commit_group;" ::: "memory"); }
template<int N> __device__ __forceinline__ void cp_wait() {
    asm volatile("cp.async.wait_group %0;" :: "n"(N) : "memory");
}
__device__ __forceinline__ void ldsm4(uint32_t a[4], uint32_t addr) {
    asm volatile("ldmatrix.sync.aligned.m8n8.x4.shared.b16 {%0,%1,%2,%3}, [%4];"
        : "=r"(a[0]), "=r"(a[1]), "=r"(a[2]), "=r"(a[3]) : "r"(addr));
}
__device__ __forceinline__ void ldsm2(uint32_t b[2], uint32_t addr) {
    asm volatile("ldmatrix.sync.aligned.m8n8.x2.shared.b16 {%0,%1}, [%2];"
        : "=r"(b[0]), "=r"(b[1]) : "r"(addr));
}
__device__ __forceinline__ void mma16816(float c[4], const uint32_t a[4], const uint32_t b[2]) {
    asm volatile("mma.sync.aligned.m16n8k16.row.col.f32.bf16.bf16.f32 "
        "{%0,%1,%2,%3}, {%4,%5,%6,%7}, {%8,%9}, {%0,%1,%2,%3};"
        : "+f"(c[0]), "+f"(c[1]), "+f"(c[2]), "+f"(c[3])
        : "r"(a[0]), "r"(a[1]), "r"(a[2]), "r"(a[3]), "r"(b[0]), "r"(b[1]));
}

// ---------------- targets dtype-detect ----------------
__global__ void ck_tgt(const void* tptr) {
    const int* p32 = (const int*)tptr;
    int lf = 1;
    for (int i = threadIdx.x; i < NN / 2; i += blockDim.x)
        if (p32[2 * i + 1] != 0) lf = 0;
    int is64 = __syncthreads_and(lf);
    const long long* p64 = (const long long*)tptr;
    for (int i = threadIdx.x; i < NN; i += blockDim.x)
        g_tg[i] = is64 ? (int)p64[i] : p32[i];
}

// ---------------- normalize + hi/lo bf16 split ----------------
__global__ void ck_norm(const float* __restrict__ x) {
    int row = blockIdx.x;
    int t = threadIdx.x;                 // 128
    const float* r = x + row * DD;
    float v[4];
    float s = 0.f;
#pragma unroll
    for (int i = 0; i < 4; i++) { v[i] = r[t + 128 * i]; s += v[i] * v[i]; }
#pragma unroll
    for (int o = 16; o > 0; o >>= 1) s += __shfl_down_sync(0xffffffffu, s, o);
    __shared__ float red[4];
    if ((t & 31) == 0) red[t >> 5] = s;
    __syncthreads();
    if (t == 0) red[0] = red[0] + red[1] + red[2] + red[3];
    __syncthreads();
    float inv = 1.0f / sqrtf(red[0]);
#pragma unroll
    for (int i = 0; i < 4; i++) {
        float xv = v[i] * inv;
        __nv_bfloat16 h = __float2bfloat16(xv);
        float lo = xv - __bfloat162float(h);
        g_hi[row * DD + t + 128 * i] = h;
        g_lo[row * DD + t + 128 * i] = __float2bfloat16(lo);
    }
}

// ---------------- online-lse helpers ----------------
__device__ __forceinline__ void lse_add(float& m, float& s, float term) {
    if (term > m) { s = s * __expf(m - term) + 1.f; m = term; }
    else          { s += __expf(term - m); }
}
__device__ __forceinline__ void lse_merge(float& m, float& s, float om, float os) {
    float M = fmaxf(m, om);
    s = s * __expf(m - M) + os * __expf(om - M);
    m = M;
}

// ---------------- mma.sync GEMM (split-bf16) + masked reductions ----------------
__global__ void __launch_bounds__(256, 1) ck_main() {
    extern __shared__ char smem[];
    const int tid = threadIdx.x;
    const int wid = tid >> 5, lane = tid & 31;
    const int wm = wid & 1, wn = wid >> 1;        // warp tile: rows wm*64, cols wn*32
    const int chunkb = blockIdx.x;
    const int rb = blockIdx.y * BM;
    const int c0b = chunkb * COLS_PER_CHUNK;
    const uint32_t sstage = smem_u32(smem) + OFF_STAGE;

    int* tcs = (int*)(smem + OFF_TCS);
    tcs[tid] = g_tg[c0b + tid];
    tcs[tid + 256] = g_tg[c0b + tid + 256];

    // staging geometry: per warp-instruction, lanes cover 4 contiguous 128B rows
    const int sj4 = (lane >> 3);                   // 0..3: row-instance within group
    const int sq = lane & 7;                       // 16B unit within row
    // ldmatrix lane geometry
    const int l7 = lane & 7;
    const int m8 = (lane >> 3) & 1;
    const int qsA = lane >> 4;                     // x4 q-select
    const int mB = (lane >> 3) & 1;                // x2 q-select
    const int g4 = lane >> 2;

    // per-thread row-state (8 rows: mf 0..3 x h 0..1)
    float m_p[8], s_p[8], mnp[8], cnt[8], m_n[8], s_n[8], mxn[8];
    int rloc[8], trow[8];
#pragma unroll
    for (int i = 0; i < 8; i++) {
        int mf = i >> 1, h = i & 1;
        rloc[i] = wm * 64 + mf * 16 + h * 8 + g4;
        trow[i] = g_tg[rb + rloc[i]];
        m_p[i] = NEGBIG; s_p[i] = 0.f; mnp[i] = 2.f; cnt[i] = 0.f;
        m_n[i] = NEGBIG; s_n[i] = 0.f; mxn[i] = -2.f;
    }

    float acc[4][4][4];
#pragma unroll
    for (int a = 0; a < 4; a++)
#pragma unroll
        for (int b = 0; b < 4; b++)
#pragma unroll
            for (int v = 0; v < 4; v++) acc[a][b][v] = 0.f;

    // stage one K-chunk of one tile into buffer buf (512 row-instances of 128B)
    auto stage = [&](int T, int c, int buf) {
        const uint32_t sbase = sstage + (uint32_t)buf * STAGE_BYTES;
#pragma unroll
        for (int j = 0; j < 16; j++) {
            int inst = (wid * 16 + j) * 4 + sj4;   // 0..511
            int half = inst >> 8;                  // 0 hi, 1 lo
            int r255 = inst & 255;
            int isB = r255 >> 7;
            int r = r255 & 127;
            int grow = isB ? (c0b + T * 128 + r) : (rb + r);
            const __nv_bfloat16* src = (half ? g_lo : g_hi) + (size_t)grow * DD + c * KC + sq * 8;
            uint32_t dst = sbase + (uint32_t)(isB * 32768 + half * 16384) + (uint32_t)r * 128u
                         + (uint32_t)(((sq ^ (r & 7))) << 4);
            cp16(dst, src);
        }
        cp_commit();
    };

    auto mma_chunk = [&](int buf) {
        const uint32_t abase = sstage + (uint32_t)buf * STAGE_BYTES;
        const uint32_t bbase = abase + 32768u;
#pragma unroll
        for (int ks = 0; ks < 4; ks++) {           // 4 k16-steps per 64-chunk
            uint32_t bh[4][2], bl[4][2];
#pragma unroll
            for (int nf = 0; nf < 4; nf++) {
                int rB = wn * 32 + nf * 8 + l7;
                uint32_t ad = bbase + (uint32_t)rB * 128u
                            + (uint32_t)((((ks * 2 + mB) ^ (rB & 7))) << 4);
                ldsm2(bh[nf], ad);
                ldsm2(bl[nf], ad + 16384u);
            }
#pragma unroll
            for (int mf = 0; mf < 4; mf++) {
                int rA = wm * 64 + mf * 16 + m8 * 8 + l7;
                uint32_t ad = abase + (uint32_t)rA * 128u
                            + (uint32_t)((((ks * 2 + qsA) ^ (rA & 7))) << 4);
                uint32_t ah[4], al[4];
                ldsm4(ah, ad);
                ldsm4(al, ad + 16384u);
#pragma unroll
                for (int nf = 0; nf < 4; nf++) {
                    mma16816(acc[mf][nf], ah, bh[nf]);   // hi*hi
                    mma16816(acc[mf][nf], ah, bl[nf]);   // hi*lo
                    mma16816(acc[mf][nf], al, bh[nf]);   // lo*hi
                }
            }
        }
    };

    stage(0, 0, 0);
    for (int T = 0; T < TILES; T++) {
        for (int c = 0; c < NCH; c++) {
            int g = T * NCH + c;
            if (g + 1 < GCH) {
                int gn = g + 1;
                stage(gn >> 3, gn & 7, gn & 1);
                cp_wait<1>();
            } else {
                cp_wait<0>();
            }
            __syncthreads();
            mma_chunk(g & 1);
            __syncthreads();
        }
        // tile epilogue (register-only; overlaps next tile's first cp.async)
#pragma unroll
        for (int mf = 0; mf < 4; mf++)
#pragma unroll
            for (int nf = 0; nf < 4; nf++) {
                int colb = T * 128 + wn * 32 + nf * 8 + (lane & 3) * 2;
#pragma unroll
                for (int v = 0; v < 4; v++) {
                    int h = v >> 1;
                    int cl = colb + (v & 1);
                    int idx = mf * 2 + h;
                    float sv = acc[mf][nf][v];
                    acc[mf][nf][v] = 0.f;
                    int tc = tcs[cl];
                    int gc = c0b + cl;
                    if (tc == trow[idx]) {
                        if (gc != rb + rloc[idx]) {
                            cnt[idx] += 1.f;
                            mnp[idx] = fminf(mnp[idx], sv);
                            float term = -F_GAMMA * fmaxf(0.f, F_OP - sv) * (sv - F_DP);
                            lse_add(m_p[idx], s_p[idx], term);
                        }
                    } else {
                        mxn[idx] = fmaxf(mxn[idx], sv);
                        float term = F_GAMMA * fmaxf(0.f, sv - F_ON) * (sv - F_DN);
                        lse_add(m_n[idx], s_n[idx], term);
                    }
                }
            }
    }

    // merge across the 4 t-lanes (lane^1, lane^2 share the same rows)
#pragma unroll
    for (int i = 0; i < 8; i++) {
#pragma unroll
        for (int o = 1; o <= 2; o <<= 1) {
            lse_merge(m_p[i], s_p[i],
                      __shfl_xor_sync(0xffffffffu, m_p[i], o),
                      __shfl_xor_sync(0xffffffffu, s_p[i], o));
            lse_merge(m_n[i], s_n[i],
                      __shfl_xor_sync(0xffffffffu, m_n[i], o),
                      __shfl_xor_sync(0xffffffffu, s_n[i], o));
            mnp[i] = fminf(mnp[i], __shfl_xor_sync(0xffffffffu, mnp[i], o));
            mxn[i] = fmaxf(mxn[i], __shfl_xor_sync(0xffffffffu, mxn[i], o));
            cnt[i] += __shfl_xor_sync(0xffffffffu, cnt[i], o);
        }
    }
    __syncthreads();                                  // stage smem now reusable
    float* red = (float*)(smem + OFF_STAGE);          // [128 rows][4 wn][8 floats]
    if ((lane & 3) == 0) {
#pragma unroll
        for (int i = 0; i < 8; i++) {
            float* p = red + ((size_t)rloc[i] * 4 + wn) * 8;
            p[0] = m_p[i]; p[1] = s_p[i]; p[2] = mnp[i]; p[3] = cnt[i];
            p[4] = m_n[i]; p[5] = s_n[i]; p[6] = mxn[i];
        }
    }
    __syncthreads();
    if (wid < 2) {                                    // 2 warps merge 128 rows
#pragma unroll
        for (int rr = lane; rr < 64; rr += 32) {
            int rl = wid * 64 + rr;
            float mp = NEGBIG, sp = 0.f, mn2 = 2.f, ct = 0.f;
            float mnn = NEGBIG, snn = 0.f, mx2 = -2.f;
#pragma unroll
            for (int s = 0; s < 4; s++) {
                const float* p = red + ((size_t)rl * 4 + s) * 8;
                lse_merge(mp, sp, p[0], p[1]);
                mn2 = fminf(mn2, p[2]); ct += p[3];
                lse_merge(mnn, snn, p[4], p[5]);
                mx2 = fmaxf(mx2, p[6]);
            }
            float* gp = &g_part[(size_t)(chunkb * NN + rb + rl) * 8];
            gp[0] = mp; gp[1] = sp; gp[2] = mn2; gp[3] = ct;
            gp[4] = mnn; gp[5] = snn; gp[6] = mx2;
        }
    }
}

// ---------------- per-row finalize ----------------
__global__ void ck_final() {
    int r = blockIdx.x * blockDim.x + threadIdx.x;
    if (r >= NN) return;
    float m_p = NEGBIG, s_p = 0.f, mnp = 2.f, cnt = 0.f;
    float m_n = NEGBIG, s_n = 0.f, mxn = -2.f;
#pragma unroll
    for (int c = 0; c < CCH; c++) {
        const float* p = &g_part[(size_t)(c * NN + r) * 8];
        float M = fmaxf(m_p, p[0]);
        s_p = s_p * expf(m_p - M) + p[1] * expf(p[0] - M);
        m_p = M;
        mnp = fminf(mnp, p[2]);
        cnt += p[3];
        M = fmaxf(m_n, p[4]);
        s_n = s_n * expf(m_n - M) + p[5] * expf(p[4] - M);
        m_n = M;
        mxn = fmaxf(mxn, p[6]);
    }
    float npos = cnt;
    float nneg = (float)(NN - 1) - npos;
    float loss = 0.f, val = 0.f;
    if (npos > 0.5f && nneg > 0.5f) {
        float lse_p, lse_n;
        {
            float th = -F_GAMMA * fmaxf(0.f, F_OP - mnp) * (mnp - F_DP);
            if (npos > 1.5f) {
                float M = fmaxf(m_p, 2.f * th);
                float S = s_p * expf(m_p - M) - expf(th - M) + expf(2.f * th - M);
                lse_p = M + logf(fmaxf(S, 1e-37f));
            } else lse_p = m_p + logf(s_p);
        }
        {
            float tn = F_GAMMA * fmaxf(0.f, mxn - F_ON) * (mxn - F_DN);
            if (nneg > 1.5f) {
                float M = fmaxf(m_n, 2.f * tn);
                float S = s_n * expf(m_n - M) - expf(tn - M) + expf(2.f * tn - M);
                lse_n = M + logf(fmaxf(S, 1e-37f));
            } else lse_n = m_n + logf(s_n);
        }
        float z = lse_p + lse_n;
        loss = fmaxf(z, 0.f) + log1pf(expf(-fabsf(z)));
        val = 1.f;
    }
    g_row[r] = loss;
    g_val[r] = val;
}

// ---------------- deterministic scalar reduction ----------------
__global__ void ck_reduce(float* __restrict__ out) {
    int t = threadIdx.x;  // 512
    float s = 0.f, v = 0.f;
    for (int i = t; i < NN; i += 512) { s += g_row[i]; v += g_val[i]; }
#pragma unroll
    for (int o = 16; o > 0; o >>= 1) {
        s += __shfl_down_sync(0xffffffffu, s, o);
        v += __shfl_down_sync(0xffffffffu, v, o);
    }
    __shared__ float ss[16], vv[16];
    if ((t & 31) == 0) { ss[t >> 5] = s; vv[t >> 5] = v; }
    __syncthreads();
    if (t < 32) {
        s = (t < 16) ? ss[t] : 0.f;
        v = (t < 16) ? vv[t] : 0.f;
#pragma unroll
        for (int o = 8; o > 0; o >>= 1) {
            s += __shfl_down_sync(0xffffffffu, s, o);
            v += __shfl_down_sync(0xffffffffu, v, o);
        }
        if (t == 0) out[0] = s / fmaxf(v, 1.f);
    }
}

extern "C" void kernel_launch(void* const* d_in, const int* in_sizes, int n_in,
                              void* d_out, int out_size) {
    const float* x = (const float*)d_in[0];
    const void* tg = d_in[1];
    float* out = (float*)d_out;
    (void)in_sizes; (void)n_in; (void)out_size;

    cudaFuncSetAttribute(ck_main, cudaFuncAttributeMaxDynamicSharedMemorySize, SMEM_TOTAL);

    ck_tgt<<<1, 256>>>(tg);
    ck_norm<<<NN, 128>>>(x);
    dim3 grid(CCH, NN / BM);
    ck_main<<<grid, 256, SMEM_TOTAL>>>();
    ck_final<<<NN / 128, 128>>>();
    ck_reduce<<<1, 512>>>(out);
}

// round 10
// speedup vs baseline: 2.5528x; 1.2265x over previous
#include <cuda_runtime.h>
#include <cuda_bf16.h>
#include <stdint.h>
#include <math.h>

#define NN 4096
#define DD 512
#define NBLK 32                     // 128-row blocks
#define NPAIR 528                   // NBLK*(NBLK+1)/2 upper-triangle tiles
#define NSLOT 32                    // partial slots per row (one per other-block)
#define KC 64                       // K elems per pipeline chunk
#define NCH (DD / KC)               // 8 chunks

#define NEGBIG (-1e30f)
#define F_GAMMA 256.0f
#define F_OP 1.25f
#define F_ON (-0.25f)
#define F_DP 0.75f
#define F_DN 0.25f

// smem: [tcs 512B][pad][stage0 64KB][stage1 64KB]; stage = Ahi(16K) Alo(16K) Bhi(16K) Blo(16K)
#define OFF_STAGE 1024
#define STAGE_BYTES 65536
#define SMEM_TOTAL (OFF_STAGE + 2 * STAGE_BYTES)   // 132096

// ---------------- scratch ----------------
__device__ __nv_bfloat16 g_hi[NN * DD];
__device__ __nv_bfloat16 g_lo[NN * DD];
__device__ int   g_tg[NN];
__device__ float g_part[NN * NSLOT * 8];   // [row][slot][8] = 4 MB
__device__ float g_row[NN];
__device__ float g_val[NN];

// ---------------- PTX helpers (sm_80-level only) ----------------
__device__ __forceinline__ uint32_t smem_u32(const void* p) {
    uint32_t a;
    asm("{ .reg .u64 t; cvta.to.shared.u64 t, %1; cvt.u32.u64 %0, t; }" : "=r"(a) : "l"(p));
    return a;
}
__device__ __forceinline__ void cp16(uint32_t dst, const void* src) {
    asm volatile("cp.async.cg.shared.global [%0], [%1], 16;" :: "r"(dst), "l"(src) : "memory");
}
__device__ __forceinline__ void cp_commit() { asm volatile("cp.async.commit_group;" ::: "memory"); }
template<int N> __device__ __forceinline__ void cp_wait() {
    asm volatile("cp.async.wait_group %0;" :: "n"(N) : "memory");
}
__device__ __forceinline__ void ldsm4(uint32_t a[4], uint32_t addr) {
    asm volatile("ldmatrix.sync.aligned.m8n8.x4.shared.b16 {%0,%1,%2,%3}, [%4];"
        : "=r"(a[0]), "=r"(a[1]), "=r"(a[2]), "=r"(a[3]) : "r"(addr));
}
__device__ __forceinline__ void ldsm2(uint32_t b[2], uint32_t addr) {
    asm volatile("ldmatrix.sync.aligned.m8n8.x2.shared.b16 {%0,%1}, [%2];"
        : "=r"(b[0]), "=r"(b[1]) : "r"(addr));
}
__device__ __forceinline__ void mma16816(float c[4], const uint32_t a[4], const uint32_t b[2]) {
    asm volatile("mma.sync.aligned.m16n8k16.row.col.f32.bf16.bf16.f32 "
        "{%0,%1,%2,%3}, {%4,%5,%6,%7}, {%8,%9}, {%0,%1,%2,%3};"
        : "+f"(c[0]), "+f"(c[1]), "+f"(c[2]), "+f"(c[3])
        : "r"(a[0]), "r"(a[1]), "r"(a[2]), "r"(a[3]), "r"(b[0]), "r"(b[1]));
}

// ---------------- targets dtype-detect ----------------
__global__ void ck_tgt(const void* tptr) {
    const int* p32 = (const int*)tptr;
    int lf = 1;
    for (int i = threadIdx.x; i < NN / 2; i += blockDim.x)
        if (p32[2 * i + 1] != 0) lf = 0;
    int is64 = __syncthreads_and(lf);
    const long long* p64 = (const long long*)tptr;
    for (int i = threadIdx.x; i < NN; i += blockDim.x)
        g_tg[i] = is64 ? (int)p64[i] : p32[i];
}

// ---------------- normalize + hi/lo bf16 split ----------------
__global__ void ck_norm(const float* __restrict__ x) {
    int row = blockIdx.x;
    int t = threadIdx.x;                 // 128
    const float* r = x + row * DD;
    float v[4];
    float s = 0.f;
#pragma unroll
    for (int i = 0; i < 4; i++) { v[i] = r[t + 128 * i]; s += v[i] * v[i]; }
#pragma unroll
    for (int o = 16; o > 0; o >>= 1) s += __shfl_down_sync(0xffffffffu, s, o);
    __shared__ float red[4];
    if ((t & 31) == 0) red[t >> 5] = s;
    __syncthreads();
    if (t == 0) red[0] = red[0] + red[1] + red[2] + red[3];
    __syncthreads();
    float inv = 1.0f / sqrtf(red[0]);
#pragma unroll
    for (int i = 0; i < 4; i++) {
        float xv = v[i] * inv;
        __nv_bfloat16 h = __float2bfloat16(xv);
        float lo = xv - __bfloat162float(h);
        g_hi[row * DD + t + 128 * i] = h;
        g_lo[row * DD + t + 128 * i] = __float2bfloat16(lo);
    }
}

// ---------------- online-lse helpers ----------------
__device__ __forceinline__ void lse_add(float& m, float& s, float term) {
    if (term > m) { s = s * __expf(m - term) + 1.f; m = term; }
    else          { s += __expf(term - m); }
}
__device__ __forceinline__ void lse_merge(float& m, float& s, float om, float os) {
    float M = fmaxf(m, om);
    s = s * __expf(m - M) + os * __expf(om - M);
    m = M;
}

// ---------------- symmetric mma.sync GEMM (split-bf16, upper triangle) ----------------
__global__ void __launch_bounds__(256, 1) ck_main() {
    extern __shared__ char smem[];
    const int tid = threadIdx.x;
    const int wid = tid >> 5, lane = tid & 31;
    const int wm = wid & 1, wn = wid >> 1;        // warp tile: rows wm*64, cols wn*32

    // decode upper-triangle pair (I <= J)
    int p = blockIdx.x, I = 0;
    while (p >= NBLK - I) { p -= NBLK - I; I++; }
    const int J = I + p;
    const int rbI = I * 128, rbJ = J * 128;
    const bool diag = (I == J);

    const uint32_t sstage = smem_u32(smem) + OFF_STAGE;
    int* tcs = (int*)smem;                         // 128 ints: J-block targets
    if (tid < 128) tcs[tid] = g_tg[rbJ + tid];

    const int sj4 = lane >> 3, sq = lane & 7;
    const int l7 = lane & 7, m8 = (lane >> 3) & 1;
    const int qsA = lane >> 4, mB = (lane >> 3) & 1, g4 = lane >> 2;

    float acc[4][4][4];
#pragma unroll
    for (int a = 0; a < 4; a++)
#pragma unroll
        for (int b = 0; b < 4; b++)
#pragma unroll
            for (int v = 0; v < 4; v++) acc[a][b][v] = 0.f;

    // stage one K-chunk: A(I rows) + B(J rows), hi+lo -> 64KB
    auto stage = [&](int c, int buf) {
        const uint32_t sbase = sstage + (uint32_t)buf * STAGE_BYTES;
#pragma unroll
        for (int j = 0; j < 16; j++) {
            int inst = wid * 64 + j * 4 + sj4;     // 0..511
            int mtx = inst >> 8;                   // 0 A, 1 B
            int half = (inst >> 7) & 1;            // 0 hi, 1 lo
            int r = inst & 127;
            int grow = (mtx ? rbJ : rbI) + r;
            const __nv_bfloat16* src = (half ? g_lo : g_hi) + (size_t)grow * DD + c * KC + sq * 8;
            uint32_t dst = sbase + (uint32_t)(mtx * 32768 + half * 16384) + (uint32_t)r * 128u
                         + (uint32_t)((sq ^ (r & 7)) << 4);
            cp16(dst, src);
        }
        cp_commit();
    };

    auto mma_chunk = [&](int buf) {
        const uint32_t abase = sstage + (uint32_t)buf * STAGE_BYTES;
        const uint32_t bbase = abase + 32768u;
#pragma unroll
        for (int ks = 0; ks < 4; ks++) {
            uint32_t bh[4][2], bl[4][2];
#pragma unroll
            for (int nf = 0; nf < 4; nf++) {
                int rB = wn * 32 + nf * 8 + l7;
                uint32_t ad = bbase + (uint32_t)rB * 128u
                            + (uint32_t)(((ks * 2 + mB) ^ (rB & 7)) << 4);
                ldsm2(bh[nf], ad);
                ldsm2(bl[nf], ad + 16384u);
            }
#pragma unroll
            for (int mf = 0; mf < 4; mf++) {
                int rA = wm * 64 + mf * 16 + m8 * 8 + l7;
                uint32_t ad = abase + (uint32_t)rA * 128u
                            + (uint32_t)(((ks * 2 + qsA) ^ (rA & 7)) << 4);
                uint32_t ah[4], al[4];
                ldsm4(ah, ad);
                ldsm4(al, ad + 16384u);
#pragma unroll
                for (int nf = 0; nf < 4; nf++) {
                    mma16816(acc[mf][nf], ah, bh[nf]);   // hi*hi
                    mma16816(acc[mf][nf], ah, bl[nf]);   // hi*lo
                    mma16816(acc[mf][nf], al, bh[nf]);   // lo*hi
                }
            }
        }
    };

    stage(0, 0);
    for (int c = 0; c < NCH; c++) {
        if (c + 1 < NCH) { stage(c + 1, (c + 1) & 1); cp_wait<1>(); }
        else             { cp_wait<0>(); }
        __syncthreads();
        mma_chunk(c & 1);
        __syncthreads();
    }

    // ---- dual-sided epilogue: rows (block I) and columns (block J) ----
    int rloc[8], trow[8];
#pragma unroll
    for (int i = 0; i < 8; i++) {
        rloc[i] = wm * 64 + (i >> 1) * 16 + (i & 1) * 8 + g4;
        trow[i] = g_tg[rbI + rloc[i]];
    }
    int cloc[8], tcol[8];
#pragma unroll
    for (int j = 0; j < 8; j++) {
        cloc[j] = wn * 32 + (j >> 1) * 8 + (lane & 3) * 2 + (j & 1);
        tcol[j] = tcs[cloc[j]];
    }
    float rm_p[8], rs_p[8], rmnp[8], rcnt[8], rm_n[8], rs_n[8], rmxn[8];
    float cm_p[8], cs_p[8], cmnp[8], ccnt[8], cm_n[8], cs_n[8], cmxn[8];
#pragma unroll
    for (int i = 0; i < 8; i++) {
        rm_p[i] = NEGBIG; rs_p[i] = 0.f; rmnp[i] = 2.f; rcnt[i] = 0.f;
        rm_n[i] = NEGBIG; rs_n[i] = 0.f; rmxn[i] = -2.f;
        cm_p[i] = NEGBIG; cs_p[i] = 0.f; cmnp[i] = 2.f; ccnt[i] = 0.f;
        cm_n[i] = NEGBIG; cs_n[i] = 0.f; cmxn[i] = -2.f;
    }
#pragma unroll
    for (int mf = 0; mf < 4; mf++)
#pragma unroll
        for (int nf = 0; nf < 4; nf++)
#pragma unroll
            for (int v = 0; v < 4; v++) {
                int idx = mf * 2 + (v >> 1);
                int jdx = nf * 2 + (v & 1);
                float sv = acc[mf][nf][v];
                if (tcol[jdx] == trow[idx]) {
                    bool offd = !diag || (rloc[idx] != cloc[jdx]);
                    if (offd) {
                        float term = -F_GAMMA * fmaxf(0.f, F_OP - sv) * (sv - F_DP);
                        rcnt[idx] += 1.f; rmnp[idx] = fminf(rmnp[idx], sv);
                        lse_add(rm_p[idx], rs_p[idx], term);
                        ccnt[jdx] += 1.f; cmnp[jdx] = fminf(cmnp[jdx], sv);
                        lse_add(cm_p[jdx], cs_p[jdx], term);
                    }
                } else {
                    float term = F_GAMMA * fmaxf(0.f, sv - F_ON) * (sv - F_DN);
                    rmxn[idx] = fmaxf(rmxn[idx], sv);
                    lse_add(rm_n[idx], rs_n[idx], term);
                    cmxn[jdx] = fmaxf(cmxn[jdx], sv);
                    lse_add(cm_n[jdx], cs_n[jdx], term);
                }
            }

    // row-side: lanes sharing same rows differ in bits 0-1
#pragma unroll
    for (int i = 0; i < 8; i++)
#pragma unroll
        for (int o = 1; o <= 2; o <<= 1) {
            lse_merge(rm_p[i], rs_p[i], __shfl_xor_sync(0xffffffffu, rm_p[i], o),
                                        __shfl_xor_sync(0xffffffffu, rs_p[i], o));
            lse_merge(rm_n[i], rs_n[i], __shfl_xor_sync(0xffffffffu, rm_n[i], o),
                                        __shfl_xor_sync(0xffffffffu, rs_n[i], o));
            rmnp[i] = fminf(rmnp[i], __shfl_xor_sync(0xffffffffu, rmnp[i], o));
            rmxn[i] = fmaxf(rmxn[i], __shfl_xor_sync(0xffffffffu, rmxn[i], o));
            rcnt[i] += __shfl_xor_sync(0xffffffffu, rcnt[i], o);
        }
    // col-side: lanes sharing same cols differ in bits 2-4
#pragma unroll
    for (int j = 0; j < 8; j++)
#pragma unroll
        for (int o = 4; o <= 16; o <<= 1) {
            lse_merge(cm_p[j], cs_p[j], __shfl_xor_sync(0xffffffffu, cm_p[j], o),
                                        __shfl_xor_sync(0xffffffffu, cs_p[j], o));
            lse_merge(cm_n[j], cs_n[j], __shfl_xor_sync(0xffffffffu, cm_n[j], o),
                                        __shfl_xor_sync(0xffffffffu, cs_n[j], o));
            cmnp[j] = fminf(cmnp[j], __shfl_xor_sync(0xffffffffu, cmnp[j], o));
            cmxn[j] = fmaxf(cmxn[j], __shfl_xor_sync(0xffffffffu, cmxn[j], o));
            ccnt[j] += __shfl_xor_sync(0xffffffffu, ccnt[j], o);
        }

    float* rred = (float*)(smem + OFF_STAGE);            // [128 rows][4 wn][8]
    float* cred = (float*)(smem + OFF_STAGE + 16384);    // [128 cols][2 wm][8]
    if ((lane & 3) == 0) {
#pragma unroll
        for (int i = 0; i < 8; i++) {
            float* q = rred + ((size_t)rloc[i] * 4 + wn) * 8;
            q[0] = rm_p[i]; q[1] = rs_p[i]; q[2] = rmnp[i]; q[3] = rcnt[i];
            q[4] = rm_n[i]; q[5] = rs_n[i]; q[6] = rmxn[i];
        }
    }
    if (lane < 4) {
#pragma unroll
        for (int j = 0; j < 8; j++) {
            float* q = cred + ((size_t)cloc[j] * 2 + wm) * 8;
            q[0] = cm_p[j]; q[1] = cs_p[j]; q[2] = cmnp[j]; q[3] = ccnt[j];
            q[4] = cm_n[j]; q[5] = cs_n[j]; q[6] = cmxn[j];
        }
    }
    __syncthreads();
    if (tid < 128) {                 // merge 4 row-partials -> g_part[rbI+tid][J]
        float mp = NEGBIG, sp = 0.f, mn2 = 2.f, ct = 0.f, mnn = NEGBIG, snn = 0.f, mx2 = -2.f;
#pragma unroll
        for (int s = 0; s < 4; s++) {
            const float* q = rred + ((size_t)tid * 4 + s) * 8;
            lse_merge(mp, sp, q[0], q[1]);
            mn2 = fminf(mn2, q[2]); ct += q[3];
            lse_merge(mnn, snn, q[4], q[5]);
            mx2 = fmaxf(mx2, q[6]);
        }
        float* gp = &g_part[(size_t)((rbI + tid) * NSLOT + J) * 8];
        gp[0] = mp; gp[1] = sp; gp[2] = mn2; gp[3] = ct;
        gp[4] = mnn; gp[5] = snn; gp[6] = mx2;
    } else if (!diag) {              // merge 2 col-partials -> g_part[rbJ+c][I]
        int c = tid - 128;
        float mp = NEGBIG, sp = 0.f, mn2 = 2.f, ct = 0.f, mnn = NEGBIG, snn = 0.f, mx2 = -2.f;
#pragma unroll
        for (int s = 0; s < 2; s++) {
            const float* q = cred + ((size_t)c * 2 + s) * 8;
            lse_merge(mp, sp, q[0], q[1]);
            mn2 = fminf(mn2, q[2]); ct += q[3];
            lse_merge(mnn, snn, q[4], q[5]);
            mx2 = fmaxf(mx2, q[6]);
        }
        float* gp = &g_part[(size_t)((rbJ + c) * NSLOT + I) * 8];
        gp[0] = mp; gp[1] = sp; gp[2] = mn2; gp[3] = ct;
        gp[4] = mnn; gp[5] = snn; gp[6] = mx2;
    }
}

// ---------------- per-row finalize: warp per row, lane = slot ----------------
__global__ void ck_final() {
    int r = (blockIdx.x * blockDim.x + threadIdx.x) >> 5;
    int lane = threadIdx.x & 31;
    if (r >= NN) return;
    const float* p = &g_part[(size_t)(r * NSLOT + lane) * 8];
    float m_p = p[0], s_p = p[1], mnp = p[2], cnt = p[3];
    float m_n = p[4], s_n = p[5], mxn = p[6];
#pragma unroll
    for (int o = 16; o > 0; o >>= 1) {
        lse_merge(m_p, s_p, __shfl_xor_sync(0xffffffffu, m_p, o),
                            __shfl_xor_sync(0xffffffffu, s_p, o));
        lse_merge(m_n, s_n, __shfl_xor_sync(0xffffffffu, m_n, o),
                            __shfl_xor_sync(0xffffffffu, s_n, o));
        mnp = fminf(mnp, __shfl_xor_sync(0xffffffffu, mnp, o));
        mxn = fmaxf(mxn, __shfl_xor_sync(0xffffffffu, mxn, o));
        cnt += __shfl_xor_sync(0xffffffffu, cnt, o);
    }
    if (lane == 0) {
        float npos = cnt;
        float nneg = (float)(NN - 1) - npos;
        float loss = 0.f, val = 0.f;
        if (npos > 0.5f && nneg > 0.5f) {
            float lse_p, lse_n;
            {
                float th = -F_GAMMA * fmaxf(0.f, F_OP - mnp) * (mnp - F_DP);
                if (npos > 1.5f) {
                    float M = fmaxf(m_p, 2.f * th);
                    float S = s_p * expf(m_p - M) - expf(th - M) + expf(2.f * th - M);
                    lse_p = M + logf(fmaxf(S, 1e-37f));
                } else lse_p = m_p + logf(s_p);
            }
            {
                float tn = F_GAMMA * fmaxf(0.f, mxn - F_ON) * (mxn - F_DN);
                if (nneg > 1.5f) {
                    float M = fmaxf(m_n, 2.f * tn);
                    float S = s_n * expf(m_n - M) - expf(tn - M) + expf(2.f * tn - M);
                    lse_n = M + logf(fmaxf(S, 1e-37f));
                } else lse_n = m_n + logf(s_n);
            }
            float z = lse_p + lse_n;
            loss = fmaxf(z, 0.f) + log1pf(expf(-fabsf(z)));
            val = 1.f;
        }
        g_row[r] = loss;
        g_val[r] = val;
    }
}

// ---------------- deterministic scalar reduction ----------------
__global__ void ck_reduce(float* __restrict__ out) {
    int t = threadIdx.x;  // 512
    float s = 0.f, v = 0.f;
    for (int i = t; i < NN; i += 512) { s += g_row[i]; v += g_val[i]; }
#pragma unroll
    for (int o = 16; o > 0; o >>= 1) {
        s += __shfl_down_sync(0xffffffffu, s, o);
        v += __shfl_down_sync(0xffffffffu, v, o);
    }
    __shared__ float ss[16], vv[16];
    if ((t & 31) == 0) { ss[t >> 5] = s; vv[t >> 5] = v; }
    __syncthreads();
    if (t < 32) {
        s = (t < 16) ? ss[t] : 0.f;
        v = (t < 16) ? vv[t] : 0.f;
#pragma unroll
        for (int o = 8; o > 0; o >>= 1) {
            s += __shfl_down_sync(0xffffffffu, s, o);
            v += __shfl_down_sync(0xffffffffu, v, o);
        }
        if (t == 0) out[0] = s / fmaxf(v, 1.f);
    }
}

extern "C" void kernel_launch(void* const* d_in, const int* in_sizes, int n_in,
                              void* d_out, int out_size) {
    const float* x = (const float*)d_in[0];
    const void* tg = d_in[1];
    float* out = (float*)d_out;
    (void)in_sizes; (void)n_in; (void)out_size;

    cudaFuncSetAttribute(ck_main, cudaFuncAttributeMaxDynamicSharedMemorySize, SMEM_TOTAL);

    ck_tgt<<<1, 256>>>(tg);
    ck_norm<<<NN, 128>>>(x);
    ck_main<<<NPAIR, 256, SMEM_TOTAL>>>();
    ck_final<<<NN / 8, 256>>>();
    ck_reduce<<<1, 512>>>(out);
}

// round 12
// speedup vs baseline: 4.8693x; 1.9075x over previous
#include <cuda_runtime.h>
#include <cuda_bf16.h>
#include <stdint.h>
#include <math.h>

#define NN 4096
#define DD 512
#define NBLK 32                     // 128-row blocks
#define NPAIR 528                   // NBLK*(NBLK+1)/2 upper-triangle tiles
#define NSLOT 32                    // partial slots per row (one per other-block)
#define KC 64                       // K elems per pipeline chunk
#define NCH (DD / KC)               // 8 chunks

#define NEGBIG (-1e30f)
#define F_GAMMA 256.0f
#define F_OP 1.25f
#define F_ON (-0.25f)
#define F_DP 0.75f
#define F_DN 0.25f

// smem: [tcs 512B][pad][stage0 32KB][stage1 32KB]; stage = A(16K) B(16K)
#define OFF_STAGE 1024
#define STAGE_BYTES 32768
#define SMEM_TOTAL (OFF_STAGE + 2 * STAGE_BYTES)   // 66560 -> 2 CTAs/SM

// ---------------- scratch ----------------
__device__ __nv_bfloat16 g_hi[NN * DD];
__device__ int   g_tg[NN];
__device__ float g_part[NN * NSLOT * 8];   // [row][slot][8] = 4 MB
__device__ float g_row[NN];
__device__ float g_val[NN];

// ---------------- PTX helpers (sm_80-level only) ----------------
__device__ __forceinline__ uint32_t smem_u32(const void* p) {
    uint32_t a;
    asm("{ .reg .u64 t; cvta.to.shared.u64 t, %1; cvt.u32.u64 %0, t; }" : "=r"(a) : "l"(p));
    return a;
}
__device__ __forceinline__ void cp16(uint32_t dst, const void* src) {
    asm volatile("cp.async.cg.shared.global [%0], [%1], 16;" :: "r"(dst), "l"(src) : "memory");
}
__device__ __forceinline__ void cp_commit() { asm volatile("cp.async.commit_group;" ::: "memory"); }
template<int N> __device__ __forceinline__ void cp_wait() {
    asm volatile("cp.async.wait_group %0;" :: "n"(N) : "memory");
}
__device__ __forceinline__ void ldsm4(uint32_t a[4], uint32_t addr) {
    asm volatile("ldmatrix.sync.aligned.m8n8.x4.shared.b16 {%0,%1,%2,%3}, [%4];"
        : "=r"(a[0]), "=r"(a[1]), "=r"(a[2]), "=r"(a[3]) : "r"(addr));
}
__device__ __forceinline__ void ldsm2(uint32_t b[2], uint32_t addr) {
    asm volatile("ldmatrix.sync.aligned.m8n8.x2.shared.b16 {%0,%1}, [%2];"
        : "=r"(b[0]), "=r"(b[1]) : "r"(addr));
}
__device__ __forceinline__ void mma16816(float c[4], const uint32_t a[4], const uint32_t b[2]) {
    asm volatile("mma.sync.aligned.m16n8k16.row.col.f32.bf16.bf16.f32 "
        "{%0,%1,%2,%3}, {%4,%5,%6,%7}, {%8,%9}, {%0,%1,%2,%3};"
        : "+f"(c[0]), "+f"(c[1]), "+f"(c[2]), "+f"(c[3])
        : "r"(a[0]), "r"(a[1]), "r"(a[2]), "r"(a[3]), "r"(b[0]), "r"(b[1]));
}

// ---------------- targets dtype-detect ----------------
__global__ void ck_tgt(const void* tptr) {
    const int* p32 = (const int*)tptr;
    int lf = 1;
    for (int i = threadIdx.x; i < NN / 2; i += blockDim.x)
        if (p32[2 * i + 1] != 0) lf = 0;
    int is64 = __syncthreads_and(lf);
    const long long* p64 = (const long long*)tptr;
    for (int i = threadIdx.x; i < NN; i += blockDim.x)
        g_tg[i] = is64 ? (int)p64[i] : p32[i];
}

// ---------------- normalize -> bf16 ----------------
__global__ void ck_norm(const float* __restrict__ x) {
    int row = blockIdx.x;
    int t = threadIdx.x;                 // 128
    const float* r = x + row * DD;
    float v[4];
    float s = 0.f;
#pragma unroll
    for (int i = 0; i < 4; i++) { v[i] = r[t + 128 * i]; s += v[i] * v[i]; }
#pragma unroll
    for (int o = 16; o > 0; o >>= 1) s += __shfl_down_sync(0xffffffffu, s, o);
    __shared__ float red[4];
    if ((t & 31) == 0) red[t >> 5] = s;
    __syncthreads();
    if (t == 0) red[0] = red[0] + red[1] + red[2] + red[3];
    __syncthreads();
    float inv = 1.0f / sqrtf(red[0]);
#pragma unroll
    for (int i = 0; i < 4; i++)
        g_hi[row * DD + t + 128 * i] = __float2bfloat16(v[i] * inv);
}

// ---------------- online-lse helpers ----------------
__device__ __forceinline__ void lse_add(float& m, float& s, float term) {
    if (term > m) { s = s * __expf(m - term) + 1.f; m = term; }
    else          { s += __expf(term - m); }
}
__device__ __forceinline__ void lse_merge(float& m, float& s, float om, float os) {
    float M = fmaxf(m, om);
    s = s * __expf(m - M) + os * __expf(om - M);
    m = M;
}

// ---------------- symmetric mma.sync GEMM (bf16, upper triangle) ----------------
__global__ void __launch_bounds__(256, 2) ck_main() {
    extern __shared__ char smem[];
    const int tid = threadIdx.x;
    const int wid = tid >> 5, lane = tid & 31;
    const int wm = wid & 1, wn = wid >> 1;        // warp tile: rows wm*64, cols wn*32

    // decode upper-triangle pair (I <= J)
    int p = blockIdx.x, I = 0;
    while (p >= NBLK - I) { p -= NBLK - I; I++; }
    const int J = I + p;
    const int rbI = I * 128, rbJ = J * 128;
    const bool diag = (I == J);

    const uint32_t sstage = smem_u32(smem) + OFF_STAGE;
    int* tcs = (int*)smem;                         // 128 ints: J-block targets
    if (tid < 128) tcs[tid] = g_tg[rbJ + tid];

    const int sj4 = lane >> 3, sq = lane & 7;
    const int l7 = lane & 7, m8 = (lane >> 3) & 1;
    const int qsA = lane >> 4, mB = (lane >> 3) & 1, g4 = lane >> 2;

    float acc[4][4][4];
#pragma unroll
    for (int a = 0; a < 4; a++)
#pragma unroll
        for (int b = 0; b < 4; b++)
#pragma unroll
            for (int v = 0; v < 4; v++) acc[a][b][v] = 0.f;

    // stage one K-chunk: A(I rows) + B(J rows) -> 32KB; 8-lane groups load full 128B rows
    auto stage = [&](int c, int buf) {
        const uint32_t sbase = sstage + (uint32_t)buf * STAGE_BYTES;
#pragma unroll
        for (int j = 0; j < 8; j++) {
            int inst = wid * 32 + j * 4 + sj4;     // 0..255 row-instances
            int mtx = inst >> 7;                   // 0 A, 1 B
            int r = inst & 127;
            int grow = (mtx ? rbJ : rbI) + r;
            const __nv_bfloat16* src = g_hi + (size_t)grow * DD + c * KC + sq * 8;
            uint32_t dst = sbase + (uint32_t)(mtx * 16384) + (uint32_t)r * 128u
                         + (uint32_t)((sq ^ (r & 7)) << 4);
            cp16(dst, src);
        }
        cp_commit();
    };

    auto mma_chunk = [&](int buf) {
        const uint32_t abase = sstage + (uint32_t)buf * STAGE_BYTES;
        const uint32_t bbase = abase + 16384u;
#pragma unroll
        for (int ks = 0; ks < 4; ks++) {
            uint32_t bh[4][2];
#pragma unroll
            for (int nf = 0; nf < 4; nf++) {
                int rB = wn * 32 + nf * 8 + l7;
                uint32_t ad = bbase + (uint32_t)rB * 128u
                            + (uint32_t)(((ks * 2 + mB) ^ (rB & 7)) << 4);
                ldsm2(bh[nf], ad);
            }
#pragma unroll
            for (int mf = 0; mf < 4; mf++) {
                int rA = wm * 64 + mf * 16 + m8 * 8 + l7;
                uint32_t ad = abase + (uint32_t)rA * 128u
                            + (uint32_t)(((ks * 2 + qsA) ^ (rA & 7)) << 4);
                uint32_t ah[4];
                ldsm4(ah, ad);
#pragma unroll
                for (int nf = 0; nf < 4; nf++)
                    mma16816(acc[mf][nf], ah, bh[nf]);
            }
        }
    };

    stage(0, 0);
    for (int c = 0; c < NCH; c++) {
        if (c + 1 < NCH) { stage(c + 1, (c + 1) & 1); cp_wait<1>(); }
        else             { cp_wait<0>(); }
        __syncthreads();
        mma_chunk(c & 1);
        __syncthreads();
    }

    // ---- dual-sided epilogue: rows (block I) and columns (block J) ----
    int rloc[8], trow[8];
#pragma unroll
    for (int i = 0; i < 8; i++) {
        rloc[i] = wm * 64 + (i >> 1) * 16 + (i & 1) * 8 + g4;
        trow[i] = g_tg[rbI + rloc[i]];
    }
    int cloc[8], tcol[8];
#pragma unroll
    for (int j = 0; j < 8; j++) {
        cloc[j] = wn * 32 + (j >> 1) * 8 + (lane & 3) * 2 + (j & 1);
        tcol[j] = tcs[cloc[j]];
    }
    float rm_p[8], rs_p[8], rmnp[8], rcnt[8], rm_n[8], rs_n[8], rmxn[8];
    float cm_p[8], cs_p[8], cmnp[8], ccnt[8], cm_n[8], cs_n[8], cmxn[8];
#pragma unroll
    for (int i = 0; i < 8; i++) {
        rm_p[i] = NEGBIG; rs_p[i] = 0.f; rmnp[i] = 2.f; rcnt[i] = 0.f;
        rm_n[i] = NEGBIG; rs_n[i] = 0.f; rmxn[i] = -2.f;
        cm_p[i] = NEGBIG; cs_p[i] = 0.f; cmnp[i] = 2.f; ccnt[i] = 0.f;
        cm_n[i] = NEGBIG; cs_n[i] = 0.f; cmxn[i] = -2.f;
    }
#pragma unroll
    for (int mf = 0; mf < 4; mf++)
#pragma unroll
        for (int nf = 0; nf < 4; nf++)
#pragma unroll
            for (int v = 0; v < 4; v++) {
                int idx = mf * 2 + (v >> 1);
                int jdx = nf * 2 + (v & 1);
                float sv = acc[mf][nf][v];
                if (tcol[jdx] == trow[idx]) {
                    bool offd = !diag || (rloc[idx] != cloc[jdx]);
                    if (offd) {
                        float term = -F_GAMMA * fmaxf(0.f, F_OP - sv) * (sv - F_DP);
                        rcnt[idx] += 1.f; rmnp[idx] = fminf(rmnp[idx], sv);
                        lse_add(rm_p[idx], rs_p[idx], term);
                        ccnt[jdx] += 1.f; cmnp[jdx] = fminf(cmnp[jdx], sv);
                        lse_add(cm_p[jdx], cs_p[jdx], term);
                    }
                } else {
                    float term = F_GAMMA * fmaxf(0.f, sv - F_ON) * (sv - F_DN);
                    rmxn[idx] = fmaxf(rmxn[idx], sv);
                    lse_add(rm_n[idx], rs_n[idx], term);
                    cmxn[jdx] = fmaxf(cmxn[jdx], sv);
                    lse_add(cm_n[jdx], cs_n[jdx], term);
                }
            }

    // row-side: lanes sharing same rows differ in bits 0-1
#pragma unroll
    for (int i = 0; i < 8; i++)
#pragma unroll
        for (int o = 1; o <= 2; o <<= 1) {
            lse_merge(rm_p[i], rs_p[i], __shfl_xor_sync(0xffffffffu, rm_p[i], o),
                                        __shfl_xor_sync(0xffffffffu, rs_p[i], o));
            lse_merge(rm_n[i], rs_n[i], __shfl_xor_sync(0xffffffffu, rm_n[i], o),
                                        __shfl_xor_sync(0xffffffffu, rs_n[i], o));
            rmnp[i] = fminf(rmnp[i], __shfl_xor_sync(0xffffffffu, rmnp[i], o));
            rmxn[i] = fmaxf(rmxn[i], __shfl_xor_sync(0xffffffffu, rmxn[i], o));
            rcnt[i] += __shfl_xor_sync(0xffffffffu, rcnt[i], o);
        }
    // col-side: lanes sharing same cols differ in bits 2-4
#pragma unroll
    for (int j = 0; j < 8; j++)
#pragma unroll
        for (int o = 4; o <= 16; o <<= 1) {
            lse_merge(cm_p[j], cs_p[j], __shfl_xor_sync(0xffffffffu, cm_p[j], o),
                                        __shfl_xor_sync(0xffffffffu, cs_p[j], o));
            lse_merge(cm_n[j], cs_n[j], __shfl_xor_sync(0xffffffffu, cm_n[j], o),
                                        __shfl_xor_sync(0xffffffffu, cs_n[j], o));
            cmnp[j] = fminf(cmnp[j], __shfl_xor_sync(0xffffffffu, cmnp[j], o));
            cmxn[j] = fmaxf(cmxn[j], __shfl_xor_sync(0xffffffffu, cmxn[j], o));
            ccnt[j] += __shfl_xor_sync(0xffffffffu, ccnt[j], o);
        }

    float* rred = (float*)(smem + OFF_STAGE);            // [128 rows][4 wn][8]
    float* cred = (float*)(smem + OFF_STAGE + 16384);    // [128 cols][2 wm][8]
    if ((lane & 3) == 0) {
#pragma unroll
        for (int i = 0; i < 8; i++) {
            float* q = rred + ((size_t)rloc[i] * 4 + wn) * 8;
            q[0] = rm_p[i]; q[1] = rs_p[i]; q[2] = rmnp[i]; q[3] = rcnt[i];
            q[4] = rm_n[i]; q[5] = rs_n[i]; q[6] = rmxn[i];
        }
    }
    if (lane < 4) {
#pragma unroll
        for (int j = 0; j < 8; j++) {
            float* q = cred + ((size_t)cloc[j] * 2 + wm) * 8;
            q[0] = cm_p[j]; q[1] = cs_p[j]; q[2] = cmnp[j]; q[3] = ccnt[j];
            q[4] = cm_n[j]; q[5] = cs_n[j]; q[6] = cmxn[j];
        }
    }
    __syncthreads();
    if (tid < 128) {                 // merge 4 row-partials -> g_part[rbI+tid][J]
        float mp = NEGBIG, sp = 0.f, mn2 = 2.f, ct = 0.f, mnn = NEGBIG, snn = 0.f, mx2 = -2.f;
#pragma unroll
        for (int s = 0; s < 4; s++) {
            const float* q = rred + ((size_t)tid * 4 + s) * 8;
            lse_merge(mp, sp, q[0], q[1]);
            mn2 = fminf(mn2, q[2]); ct += q[3];
            lse_merge(mnn, snn, q[4], q[5]);
            mx2 = fmaxf(mx2, q[6]);
        }
        float* gp = &g_part[(size_t)((rbI + tid) * NSLOT + J) * 8];
        gp[0] = mp; gp[1] = sp; gp[2] = mn2; gp[3] = ct;
        gp[4] = mnn; gp[5] = snn; gp[6] = mx2;
    } else if (!diag) {              // merge 2 col-partials -> g_part[rbJ+c][I]
        int c = tid - 128;
        float mp = NEGBIG, sp = 0.f, mn2 = 2.f, ct = 0.f, mnn = NEGBIG, snn = 0.f, mx2 = -2.f;
#pragma unroll
        for (int s = 0; s < 2; s++) {
            const float* q = cred + ((size_t)c * 2 + s) * 8;
            lse_merge(mp, sp, q[0], q[1]);
            mn2 = fminf(mn2, q[2]); ct += q[3];
            lse_merge(mnn, snn, q[4], q[5]);
            mx2 = fmaxf(mx2, q[6]);
        }
        float* gp = &g_part[(size_t)((rbJ + c) * NSLOT + I) * 8];
        gp[0] = mp; gp[1] = sp; gp[2] = mn2; gp[3] = ct;
        gp[4] = mnn; gp[5] = snn; gp[6] = mx2;
    }
}

// ---------------- per-row finalize: warp per row, lane = slot ----------------
__global__ void ck_final() {
    int r = (blockIdx.x * blockDim.x + threadIdx.x) >> 5;
    int lane = threadIdx.x & 31;
    if (r >= NN) return;
    const float* p = &g_part[(size_t)(r * NSLOT + lane) * 8];
    float m_p = p[0], s_p = p[1], mnp = p[2], cnt = p[3];
    float m_n = p[4], s_n = p[5], mxn = p[6];
#pragma unroll
    for (int o = 16; o > 0; o >>= 1) {
        lse_merge(m_p, s_p, __shfl_xor_sync(0xffffffffu, m_p, o),
                            __shfl_xor_sync(0xffffffffu, s_p, o));
        lse_merge(m_n, s_n, __shfl_xor_sync(0xffffffffu, m_n, o),
                            __shfl_xor_sync(0xffffffffu, s_n, o));
        mnp = fminf(mnp, __shfl_xor_sync(0xffffffffu, mnp, o));
        mxn = fmaxf(mxn, __shfl_xor_sync(0xffffffffu, mxn, o));
        cnt += __shfl_xor_sync(0xffffffffu, cnt, o);
    }
    if (lane == 0) {
        float npos = cnt;
        float nneg = (float)(NN - 1) - npos;
        float loss = 0.f, val = 0.f;
        if (npos > 0.5f && nneg > 0.5f) {
            float lse_p, lse_n;
            {
                float th = -F_GAMMA * fmaxf(0.f, F_OP - mnp) * (mnp - F_DP);
                if (npos > 1.5f) {
                    float M = fmaxf(m_p, 2.f * th);
                    float S = s_p * expf(m_p - M) - expf(th - M) + expf(2.f * th - M);
                    lse_p = M + logf(fmaxf(S, 1e-37f));
                } else lse_p = m_p + logf(s_p);
            }
            {
                float tn = F_GAMMA * fmaxf(0.f, mxn - F_ON) * (mxn - F_DN);
                if (nneg > 1.5f) {
                    float M = fmaxf(m_n, 2.f * tn);
                    float S = s_n * expf(m_n - M) - expf(tn - M) + expf(2.f * tn - M);
                    lse_n = M + logf(fmaxf(S, 1e-37f));
                } else lse_n = m_n + logf(s_n);
            }
            float z = lse_p + lse_n;
            loss = fmaxf(z, 0.f) + log1pf(expf(-fabsf(z)));
            val = 1.f;
        }
        g_row[r] = loss;
        g_val[r] = val;
    }
}

// ---------------- deterministic scalar reduction ----------------
__global__ void ck_reduce(float* __restrict__ out) {
    int t = threadIdx.x;  // 512
    float s = 0.f, v = 0.f;
    for (int i = t; i < NN; i += 512) { s += g_row[i]; v += g_val[i]; }
#pragma unroll
    for (int o = 16; o > 0; o >>= 1) {
        s += __shfl_down_sync(0xffffffffu, s, o);
        v += __shfl_down_sync(0xffffffffu, v, o);
    }
    __shared__ float ss[16], vv[16];
    if ((t & 31) == 0) { ss[t >> 5] = s; vv[t >> 5] = v; }
    __syncthreads();
    if (t < 32) {
        s = (t < 16) ? ss[t] : 0.f;
        v = (t < 16) ? vv[t] : 0.f;
#pragma unroll
        for (int o = 8; o > 0; o >>= 1) {
            s += __shfl_down_sync(0xffffffffu, s, o);
            v += __shfl_down_sync(0xffffffffu, v, o);
        }
        if (t == 0) out[0] = s / fmaxf(v, 1.f);
    }
}

extern "C" void kernel_launch(void* const* d_in, const int* in_sizes, int n_in,
                              void* d_out, int out_size) {
    const float* x = (const float*)d_in[0];
    const void* tg = d_in[1];
    float* out = (float*)d_out;
    (void)in_sizes; (void)n_in; (void)out_size;

    cudaFuncSetAttribute(ck_main, cudaFuncAttributeMaxDynamicSharedMemorySize, SMEM_TOTAL);

    ck_tgt<<<1, 256>>>(tg);
    ck_norm<<<NN, 128>>>(x);
    ck_main<<<NPAIR, 256, SMEM_TOTAL>>>();
    ck_final<<<NN / 8, 256>>>();
    ck_reduce<<<1, 512>>>(out);
}